// round 11
// baseline (speedup 1.0000x reference)
#include <cuda_runtime.h>
#include <math.h>

// Problem constants (fixed: point_cloud [8, 4096, 3], K=20)
#define BATCH 8
#define NPTS  4096
#define KNN   20
#define TPB   512
#define WARPS (TPB / 32)          // 16 warps per CTA
#define CPB   55                  // CTAs per batch -> grid = 440 (one balanced wave @3/SM)
#define FULLM 0xFFFFFFFFu

__global__ __launch_bounds__(TPB, 3)
void knn_warp_kernel(const float* __restrict__ pc, float* __restrict__ out)
{
    // Whole batch staged as float4 (x, y, z, |p|^2): 64 KB dynamic smem.
    extern __shared__ float4 pts[];
    __shared__ int qctr;

    const int b   = blockIdx.x / CPB;
    const int cta = blockIdx.x % CPB;
    const float* __restrict__ pcb = pc + (size_t)b * NPTS * 3;

    if (threadIdx.x == 0) qctr = 0;
    for (int i = threadIdx.x; i < NPTS; i += TPB) {
        float x = pcb[3 * i + 0];
        float y = pcb[3 * i + 1];
        float z = pcb[3 * i + 2];
        pts[i] = make_float4(x, y, z, fmaf(x, x, fmaf(y, y, z * z)));
    }
    __syncthreads();

    const int lane = threadIdx.x & 31;

    // Query range for this CTA (~74-75 queries), stolen one at a time by warps.
    const int qstart = (NPTS * cta) / CPB;
    const int qcount = (NPTS * (cta + 1)) / CPB - qstart;

    const long long BNK = (long long)BATCH * NPTS * KNN;
    float* __restrict__ srcA  = out;
    float* __restrict__ tgtA  = out + BNK;
    float* __restrict__ attA  = out + 2 * BNK;
    float* __restrict__ slocA = out + 3 * BNK;

    for (;;) {
        int t;
        if (lane == 0) t = atomicAdd(&qctr, 1);
        t = __shfl_sync(FULLM, t, 0);
        if (t >= qcount) break;
        const int qi = qstart + t;

        const float4 q = pts[qi];
        const float nx = -2.0f * q.x, ny = -2.0f * q.y, nz = -2.0f * q.z;
        const float sqq = fmaf(q.x, q.x, fmaf(q.y, q.y, q.z * q.z));

        // Ranking key r = |p|^2 - 2 q.p  (= d^2 - |q|^2): constant shift of d^2,
        // so selection order and ties are identical; d^2 restored in epilogue.
        // Lane-sorted list: lane l holds the (l+1)-th smallest (r, idx).
        // Exactness for lanes 0..21: admission thr (lane-21 snapshot) is
        // conservative/stale; a candidate >= current lane-31 value yields an
        // all-false pred and is dropped -- provably outside the exact top-22.
        float ld;
        int   li = lane;
        float r1s, r2s, r3s;                      // batch-0 leftovers (32/64/96+lane)
        {
            float4 p0 = pts[lane];
            float4 p1 = pts[32 + lane];
            float4 p2 = pts[64 + lane];
            float4 p3 = pts[96 + lane];
            ld  = fmaf(nx, p0.x, fmaf(ny, p0.y, fmaf(nz, p0.z, p0.w)));
            r1s = fmaf(nx, p1.x, fmaf(ny, p1.y, fmaf(nz, p1.z, p1.w)));
            r2s = fmaf(nx, p2.x, fmaf(ny, p2.y, fmaf(nz, p2.z, p2.w)));
            r3s = fmaf(nx, p3.x, fmaf(ny, p3.y, fmaf(nz, p3.z, p3.w)));
        }

        // ---- seed: exact bitonic sort of candidates 0..31 ----------------
        // Lexicographic (r, idx): identical semantics to stable insertion.
#pragma unroll
        for (int k = 2; k <= 32; k <<= 1) {
#pragma unroll
            for (int j = k >> 1; j > 0; j >>= 1) {
                float od = __shfl_xor_sync(FULLM, ld, j);
                int   oi = __shfl_xor_sync(FULLM, li, j);
                bool up     = (lane & k) == 0;
                bool iLower = (lane & j) == 0;
                bool oless  = (od < ld) || ((od == ld) && (oi < li));
                bool take   = (iLower == up) ? oless : !oless;
                if (take) { ld = od; li = oi; }
            }
        }
        float thr = __shfl_sync(FULLM, ld, 21);

        // Stable serial insert of admitted candidates (ascending index).
        auto drain = [&](unsigned m, float dval, int jbase) {
            while (m) {
                int srcl = __ffs(m) - 1; m &= m - 1;
                float cd = __shfl_sync(FULLM, dval, srcl);
                int   cj = jbase + srcl;
                float ud = __shfl_up_sync(FULLM, ld, 1);
                int   ui = __shfl_up_sync(FULLM, li, 1);
                bool pred  = cd < ld;                 // strict: stable ties
                bool predp = (lane > 0) && (cd < ud);
                if (pred) {
                    ld = predp ? ud : cd;
                    li = predp ? ui : cj;
                }
            }
        };

        // ---- batch-0 remainder: candidates 32..127 -----------------------
        {
            float mmin = fminf(r1s, fminf(r2s, r3s));
            if (__ballot_sync(FULLM, mmin < thr)) {
                unsigned m1 = __ballot_sync(FULLM, r1s < thr);
                unsigned m2 = __ballot_sync(FULLM, r2s < thr);
                unsigned m3 = __ballot_sync(FULLM, r3s < thr);
                drain(m1, r1s, 32);
                drain(m2, r2s, 64);
                drain(m3, r3s, 96);
                thr = __shfl_sync(FULLM, ld, 21);
            }
        }

        // ---- main batches: 128 candidates each (s = 1..31) ---------------
#pragma unroll 2
        for (int s = 1; s < NPTS / 128; s++) {
            const int j0 = s * 128;
            float4 p0 = pts[j0 + lane];
            float4 p1 = pts[j0 + 32 + lane];
            float4 p2 = pts[j0 + 64 + lane];
            float4 p3 = pts[j0 + 96 + lane];
            float r0 = fmaf(nx, p0.x, fmaf(ny, p0.y, fmaf(nz, p0.z, p0.w)));
            float r1 = fmaf(nx, p1.x, fmaf(ny, p1.y, fmaf(nz, p1.z, p1.w)));
            float r2 = fmaf(nx, p2.x, fmaf(ny, p2.y, fmaf(nz, p2.z, p2.w)));
            float r3 = fmaf(nx, p3.x, fmaf(ny, p3.y, fmaf(nz, p3.z, p3.w)));

            float mmin = fminf(fminf(r0, r1), fminf(r2, r3));
            if (__ballot_sync(FULLM, mmin < thr)) {
                unsigned m0 = __ballot_sync(FULLM, r0 < thr);
                unsigned m1 = __ballot_sync(FULLM, r1 < thr);
                unsigned m2 = __ballot_sync(FULLM, r2 < thr);
                unsigned m3 = __ballot_sync(FULLM, r3 < thr);
                drain(m0, r0, j0);
                drain(m1, r1, j0 + 32);
                drain(m2, r2, j0 + 64);
                drain(m3, r3, j0 + 96);
                thr = __shfl_sync(FULLM, ld, 21);     // refresh once per batch
            }
        }

        // ---- epilogue: lane 0 = self (r strictly minimal); lanes 1..20 ---
        const int row = b * NPTS + qi;
        float d2l = fmaxf(ld + sqq, 0.0f);            // back to true d^2
        float dk2 = __shfl_sync(FULLM, d2l, 20);      // k-th neighbor d^2
        float dk = sqrtf(dk2);
        float sigma = dk + 1e-6f;                     // BETA = 1
        float inv2s2 = 1.0f / (2.0f * sigma * sigma);

        const long long base = (long long)row * KNN;
        if (lane >= 1 && lane <= KNN) {
            int k = lane - 1;
            srcA[base + k] = (float)row;
            tgtA[base + k] = (float)(b * NPTS + li);
            attA[base + k] = expf(-d2l * inv2s2);
        }
        if (lane == 0) slocA[row] = dk * dk;          // LAMBDA = 1
    }
}

extern "C" void kernel_launch(void* const* d_in, const int* in_sizes, int n_in,
                              void* d_out, int out_size)
{
    (void)in_sizes; (void)n_in; (void)out_size;
    const float* pc = (const float*)d_in[0];
    float* outp = (float*)d_out;

    const size_t smem = (size_t)NPTS * sizeof(float4);   // 64 KB
    cudaFuncSetAttribute(knn_warp_kernel,
                         cudaFuncAttributeMaxDynamicSharedMemorySize, (int)smem);
    knn_warp_kernel<<<BATCH * CPB, TPB, smem>>>(pc, outp);
}